// round 16
// baseline (speedup 1.0000x reference)
#include <cuda_runtime.h>
#include <cuda_fp16.h>
#include <math.h>
#include <stdint.h>

#define BB  2
#define SS  2048
#define DM  1024
#define NH  16
#define DKK 64

// Scratch (allocation-free rule: __device__ globals)
__device__ __half g_Qh[BB*NH*SS*DKK];   // [b][h][s][dk] fp16
__device__ __half g_Kh[BB*NH*SS*DKK];   // [b][h][s][dk] fp16
__device__ __half g_Vt[BB*NH*DKK*SS];   // [b][h][dk][s] fp16 (TRANSPOSED)
__device__ __half g_Ohh[BB*SS*DM];      // [b][s][h*64+dk] fp16
__device__ __half g_qh[BB*SS*DM];       // pre-converted q (fp16)
__device__ __half g_kh[BB*SS*DM];       // pre-converted k (fp16)
__device__ __half g_Wh[4*DM*DM];        // pre-converted Wq,Wk,Wv,Wo (fp16)

// ---------------------------------------------------------------------------
// helpers
// ---------------------------------------------------------------------------
__device__ __forceinline__ void mma_f16(float c[4], const uint32_t a[4], const uint32_t b[2]) {
    asm volatile(
        "mma.sync.aligned.m16n8k16.row.col.f32.f16.f16.f32 "
        "{%0,%1,%2,%3}, {%4,%5,%6,%7}, {%8,%9}, {%0,%1,%2,%3};\n"
        : "+f"(c[0]), "+f"(c[1]), "+f"(c[2]), "+f"(c[3])
        : "r"(a[0]), "r"(a[1]), "r"(a[2]), "r"(a[3]), "r"(b[0]), "r"(b[1]));
}

__device__ __forceinline__ void ldsm_x4(uint32_t r[4], uint32_t saddr) {
    asm volatile("ldmatrix.sync.aligned.m8n8.x4.shared.b16 {%0,%1,%2,%3}, [%4];"
        : "=r"(r[0]), "=r"(r[1]), "=r"(r[2]), "=r"(r[3]) : "r"(saddr));
}

__device__ __forceinline__ float ex2f(float x) {
    float y;
    asm("ex2.approx.f32 %0, %1;" : "=f"(y) : "f"(x));
    return y;
}

__device__ __forceinline__ uint32_t packh2(float x, float y) {
    __half2 h = __floats2half2_rn(x, y);
    return *(uint32_t*)&h;
}

__device__ __forceinline__ void cp16(void* dst, const void* src) {
    uint32_t d = (uint32_t)__cvta_generic_to_shared(dst);
    asm volatile("cp.async.cg.shared.global [%0], [%1], 16;" :: "r"(d), "l"(src));
}
__device__ __forceinline__ void cp_commit() { asm volatile("cp.async.commit_group;"); }
__device__ __forceinline__ void cp_wait0()  { asm volatile("cp.async.wait_group 0;"); }
__device__ __forceinline__ void cp_wait1()  { asm volatile("cp.async.wait_group 1;"); }

// 0.125 * log2(e)
#define SC_LOG2E 0.18033688f

// ---------------------------------------------------------------------------
// Fused fp32 -> fp16 (RN) pre-pass over q, k, Wq, Wk, Wv, Wo.  ILP=2.
// ---------------------------------------------------------------------------
#define NQ4 (BB*SS*DM/4)   // 1048576 float4
#define NW4 (DM*DM/4)      // 262144 float4
#define NCVT4 (2*NQ4 + 4*NW4)    // 3145728
#define NCVT_HALF (NCVT4 / 2)

__device__ __forceinline__ void cvt_one(
    int i, const float* q, const float* k,
    const float* Wq, const float* Wk, const float* Wv, const float* Wo,
    __half* qh, __half* kh, __half* Wh)
{
    const float4* src; __half* dsth; int off;
    if (i < NQ4)            { src = (const float4*)q;  dsth = qh; off = i; }
    else if (i < 2 * NQ4)   { src = (const float4*)k;  dsth = kh; off = i - NQ4; }
    else {
        int j = i - 2 * NQ4;
        int w = j / NW4; off = j - w * NW4;
        src = (const float4*)(w == 0 ? Wq : w == 1 ? Wk : w == 2 ? Wv : Wo);
        dsth = Wh + (size_t)w * DM * DM;
    }
    float4 d = src[off];
    __half2 h0 = __floats2half2_rn(d.x, d.y);
    __half2 h1 = __floats2half2_rn(d.z, d.w);
    uint2 e;
    e.x = *(uint32_t*)&h0;
    e.y = *(uint32_t*)&h1;
    ((uint2*)dsth)[off] = e;
}

__global__ void cvt_all(const float* __restrict__ q, const float* __restrict__ k,
                        const float* __restrict__ Wq, const float* __restrict__ Wk,
                        const float* __restrict__ Wv, const float* __restrict__ Wo,
                        __half* __restrict__ qh, __half* __restrict__ kh,
                        __half* __restrict__ Wh)
{
    int i = blockIdx.x * blockDim.x + threadIdx.x;
    if (i >= NCVT_HALF) return;
    cvt_one(i,             q, k, Wq, Wk, Wv, Wo, qh, kh, Wh);
    cvt_one(i + NCVT_HALF, q, k, Wq, Wk, Wv, Wo, qh, kh, Wh);
}

// ---------------------------------------------------------------------------
// fp16 GEMM core (round-14/15 proven): m16n8k16 mma, cp.async double-buffered,
// BK=64, single sync per k-tile, ldmatrix fragments, stride 72.
// bx = N-block index (passed explicitly for grid folding).
// mode 0: fp32 row-major; mode 1: fp16 head-split; mode 2: fp16 transposed.
// ---------------------------------------------------------------------------
#define HA(buf) ((buf) * 9216)              // halves: 128*72 per tile
#define HB(buf) (18432 + (buf) * 9216)
#define GEMM_SMEM_BYTES (36864 * 2)         // 73728

__device__ __forceinline__ void gemm_core_h(
    const __half* __restrict__ X, const __half* __restrict__ W,
    const float* __restrict__ bias, float* __restrict__ Yf,
    __half* __restrict__ Yh, int mode, __half* sm, int bx)
{
    const int bm = blockIdx.y * 128;
    const int bn = bx * 128;
    const int tid = threadIdx.x;
    const int lane = tid & 31, wid = tid >> 5;
    const int wm = wid >> 1;
    const int wn = wid & 1;
    const int grp = lane >> 2;
    const int tig = lane & 3;

    const int l15 = lane & 15;
    const int lh8 = (lane >> 4) * 8;
    const int l7  = lane & 7;
    const int l38 = ((lane >> 3) & 1) * 8;

    const int ldrow = tid >> 3;     // 0..15
    const int ldc   = tid & 7;      // 0..7

    float c[4][8][4];
    #pragma unroll
    for (int t = 0; t < 4; t++)
        #pragma unroll
        for (int u = 0; u < 8; u++)
            #pragma unroll
            for (int r = 0; r < 4; r++) c[t][u][r] = 0.f;

    #pragma unroll
    for (int i = 0; i < 8; i++) {
        int row = ldrow + i * 16;
        cp16(sm + HA(0) + row * 72 + ldc * 8, X + (size_t)(bm + row) * DM + ldc * 8);
        cp16(sm + HB(0) + row * 72 + ldc * 8, W + (size_t)(bn + row) * DM + ldc * 8);
    }
    cp_commit();

    const int NT = DM / 64;   // 16
    for (int kt = 0; kt < NT; kt++) {
        cp_wait0();
        __syncthreads();

        if (kt + 1 < NT) {
            int k0n = (kt + 1) * 64;
            int bufn = (kt + 1) & 1;
            #pragma unroll
            for (int i = 0; i < 8; i++) {
                int row = ldrow + i * 16;
                cp16(sm + HA(bufn) + row * 72 + ldc * 8, X + (size_t)(bm + row) * DM + k0n + ldc * 8);
                cp16(sm + HB(bufn) + row * 72 + ldc * 8, W + (size_t)(bn + row) * DM + k0n + ldc * 8);
            }
            cp_commit();
        }

        const uint32_t As_b = (uint32_t)__cvta_generic_to_shared(sm + HA(kt & 1));
        const uint32_t Bs_b = (uint32_t)__cvta_generic_to_shared(sm + HB(kt & 1));

        #pragma unroll
        for (int s = 0; s < 4; s++) {
            const int ck = s * 16;
            uint32_t a[4][4];
            uint32_t b[8][2];
            #pragma unroll
            for (int t = 0; t < 4; t++)
                ldsm_x4(a[t], As_b + 2u * ((wm * 64 + t * 16 + l15) * 72 + ck + lh8));
            #pragma unroll
            for (int up = 0; up < 4; up++) {
                uint32_t tmp[4];
                ldsm_x4(tmp, Bs_b + 2u * ((wn * 64 + up * 16 + lh8 + l7) * 72 + ck + l38));
                b[2*up][0] = tmp[0]; b[2*up][1] = tmp[1];
                b[2*up+1][0] = tmp[2]; b[2*up+1][1] = tmp[3];
            }
            #pragma unroll
            for (int t = 0; t < 4; t++)
                #pragma unroll
                for (int u = 0; u < 8; u++)
                    mma_f16(c[t][u], a[t], b[u]);
        }
    }

    #pragma unroll
    for (int t = 0; t < 4; t++) {
        #pragma unroll
        for (int u = 0; u < 8; u++) {
            int r0  = bm + wm * 64 + t * 16 + grp;
            int col = bn + wn * 64 + u * 8 + 2 * tig;
            float2 bv = *(const float2*)(bias + col);
            #pragma unroll
            for (int half = 0; half < 2; half++) {
                int m = r0 + half * 8;
                float vx = c[t][u][half * 2 + 0] + bv.x;
                float vy = c[t][u][half * 2 + 1] + bv.y;
                int b_ = m >> 11, s_ = m & 2047;
                int h_ = col >> 6, dk = col & 63;
                if (mode == 1) {
                    __half2 hv = __floats2half2_rn(vx, vy);
                    *(__half2*)(Yh + (((size_t)b_ * NH + h_) * SS + s_) * DKK + dk) = hv;
                } else if (mode == 2) {
                    size_t base = ((size_t)b_ * NH + h_) * DKK;
                    Yh[(base + dk)     * SS + s_] = __float2half_rn(vx);
                    Yh[(base + dk + 1) * SS + s_] = __float2half_rn(vy);
                } else {
                    *(float2*)(Yf + (size_t)m * DM + col) = make_float2(vx, vy);
                }
            }
        }
    }
}

// Fused Q/K/V projection: projection index folded into blockIdx.x (fastest)
// so same-(bm,bn) blocks across projections co-schedule -> X tiles of the
// K/V projections (same kh input) hit L2 on the 2nd/3rd read.
struct QKVArgs {
    const __half *xq, *xk;
    const __half *w0, *w1, *w2;
    const float *b0, *b1, *b2;
    __half *y0, *y1, *y2;   // y0,y1: head-split; y2: transposed
};

__global__ __launch_bounds__(128, 2)
void gemm_qkv(QKVArgs a)
{
    extern __shared__ __half smh[];
    const int z  = blockIdx.x % 3;
    const int bx = blockIdx.x / 3;
    const __half* X = (z == 0) ? a.xq : a.xk;
    const __half* W = (z == 0) ? a.w0 : (z == 1) ? a.w1 : a.w2;
    const float*  B = (z == 0) ? a.b0 : (z == 1) ? a.b1 : a.b2;
    __half*       Y = (z == 0) ? a.y0 : (z == 1) ? a.y1 : a.y2;
    gemm_core_h(X, W, B, nullptr, Y, (z == 2) ? 2 : 1, smh, bx);
}

__global__ __launch_bounds__(128, 2)
void gemm_h(const __half* __restrict__ X, const __half* __restrict__ W,
            const float* __restrict__ bias, float* __restrict__ Y)
{
    extern __shared__ __half smh[];
    gemm_core_h(X, W, bias, Y, nullptr, 0, smh, blockIdx.x);
}

// ---------------------------------------------------------------------------
// Flash attention (round-15 proven): warp-row tiling, P in registers,
// shuffle-only softmax, fp16 mma, ldmatrix K/V, additive kmask bias,
// diag-only causal, ex2, cp.async pipeline. kbias loads vectorized (float2).
// ---------------------------------------------------------------------------
#define FLH_K0 0
#define FLH_K1 4608
#define FLH_V  9216
#define FL_SMEM_BYTES (13824 * 2 + 512 + 128)   // 28288

__global__ __launch_bounds__(128, 3)
void flash_attn_h(const int* __restrict__ q_mask, const int* __restrict__ k_mask,
                  const int* __restrict__ causal_flag, int causal_default)
{
    extern __shared__ float fsm[];
    __half* hsm = (__half*)fsm;
    __half* Vts = hsm + FLH_V;
    float* kbias = fsm + 6912;   // [2][64]

    const int b  = blockIdx.z, h = blockIdx.y;
    const int q0 = ((int)gridDim.x - 1 - (int)blockIdx.x) * 64;  // longest-first
    const int tid = threadIdx.x;
    const int lane = tid & 31, wid = tid >> 5;
    const int grp = lane >> 2;
    const int tig = lane & 3;
    const int causal = causal_flag ? causal_flag[0] : causal_default;

    const int l15 = lane & 15;
    const int lh8 = (lane >> 4) * 8;
    const int l7  = lane & 7;
    const int l38 = ((lane >> 3) & 1) * 8;

    const __half* Qb  = g_Qh + (((size_t)b * NH + h) * SS) * DKK;
    const __half* Kb  = g_Kh + (((size_t)b * NH + h) * SS) * DKK;
    const __half* Vtb = g_Vt + (((size_t)b * NH + h) * DKK) * SS;

    const int ldrow = tid >> 3;   // 0..15
    const int ldc   = tid & 7;    // 0..7

    // ---- prologue: cp.async K(0) -> K0, Q -> V buffer (one group); kbias(0) ----
    #pragma unroll
    for (int i = 0; i < 4; i++) {
        int row = ldrow + i * 16;
        cp16(hsm + FLH_K0 + row * 72 + ldc * 8, Kb + (size_t)row * DKK + ldc * 8);
        cp16(Vts + row * 72 + ldc * 8, Qb + (size_t)(q0 + row) * DKK + ldc * 8);
    }
    cp_commit();
    if (tid < 64) kbias[tid] = k_mask[(size_t)b * SS + tid] ? 0.f : -INFINITY;
    cp_wait0();
    __syncthreads();

    // ---- extract Q fragments (rows wid*16..+15) from V buffer ----
    const uint32_t Vts_b = (uint32_t)__cvta_generic_to_shared(Vts);
    uint32_t qf[4][4];
    #pragma unroll
    for (int s16 = 0; s16 < 4; s16++)
        ldsm_x4(qf[s16], Vts_b + 2u * ((wid * 16 + l15) * 72 + s16 * 16 + lh8));

    float o[8][4];
    #pragma unroll
    for (int u = 0; u < 8; u++)
        #pragma unroll
        for (int r = 0; r < 4; r++) o[u][r] = 0.f;

    float m_r[2] = {-INFINITY, -INFINITY};
    float l_r[2] = {0.f, 0.f};

    const int nkt = causal ? (q0 >> 6) + 1 : (SS / 64);

    for (int kt = 0; kt < nkt; kt++) {
        const int k0 = kt * 64;
        const uint32_t Kc_b = (uint32_t)__cvta_generic_to_shared(
            hsm + ((kt & 1) ? FLH_K1 : FLH_K0));
        __half* Kn = hsm + ((kt & 1) ? FLH_K0 : FLH_K1);
        const float* kbc = kbias + (kt & 1) * 64;
        const bool diag = causal && (kt == nkt - 1);

        cp_wait0();        // K(t) landed (V(t-1)/Q already consumed)
        __syncthreads();   // S1: K(t) visible; V buffer free (PV/qf done)

        // ---- issue V(t) ----
        #pragma unroll
        for (int i = 0; i < 4; i++) {
            int row = ldrow + i * 16;
            cp16(Vts + row * 72 + ldc * 8, Vtb + (size_t)row * SS + k0 + ldc * 8);
        }
        cp_commit();   // group: V(t)

        // ---- S = Q K^T (warp covers all 64 keys) ----
        float sacc[8][4];
        #pragma unroll
        for (int u = 0; u < 8; u++)
            #pragma unroll
            for (int r = 0; r < 4; r++) sacc[u][r] = 0.f;

        #pragma unroll
        for (int s16 = 0; s16 < 4; s16++) {
            const int ck = s16 * 16;
            uint32_t kb2[8][2];
            #pragma unroll
            for (int up = 0; up < 4; up++) {
                uint32_t tmp[4];
                ldsm_x4(tmp, Kc_b + 2u * ((up * 16 + lh8 + l7) * 72 + ck + l38));
                kb2[2*up][0] = tmp[0]; kb2[2*up][1] = tmp[1];
                kb2[2*up+1][0] = tmp[2]; kb2[2*up+1][1] = tmp[3];
            }
            #pragma unroll
            for (int u = 0; u < 8; u++)
                mma_f16(sacc[u], qf[s16], kb2[u]);
        }

        // ---- scale(log2) + kmask bias (float2); causal only on diagonal ----
        const int r0 = q0 + wid * 16 + grp;
        const int r1 = r0 + 8;
        #pragma unroll
        for (int u = 0; u < 8; u++) {
            int cl = u * 8 + 2 * tig;
            float2 kbv = *(const float2*)(kbc + cl);
            float x0 = fmaf(sacc[u][0], SC_LOG2E, kbv.x);
            float x1 = fmaf(sacc[u][1], SC_LOG2E, kbv.y);
            float x2 = fmaf(sacc[u][2], SC_LOG2E, kbv.x);
            float x3 = fmaf(sacc[u][3], SC_LOG2E, kbv.y);
            if (diag) {
                int kg = k0 + cl;
                if (kg     > r0) x0 = -INFINITY;
                if (kg + 1 > r0) x1 = -INFINITY;
                if (kg     > r1) x2 = -INFINITY;
                if (kg + 1 > r1) x3 = -INFINITY;
            }
            sacc[u][0] = x0; sacc[u][1] = x1;
            sacc[u][2] = x2; sacc[u][3] = x3;
        }

        // ---- row max: pure quad shuffles ----
        float mx0 = -INFINITY, mx1 = -INFINITY;
        #pragma unroll
        for (int u = 0; u < 8; u++) {
            mx0 = fmaxf(mx0, fmaxf(sacc[u][0], sacc[u][1]));
            mx1 = fmaxf(mx1, fmaxf(sacc[u][2], sacc[u][3]));
        }
        mx0 = fmaxf(mx0, __shfl_xor_sync(0xffffffffu, mx0, 1));
        mx0 = fmaxf(mx0, __shfl_xor_sync(0xffffffffu, mx0, 2));
        mx1 = fmaxf(mx1, __shfl_xor_sync(0xffffffffu, mx1, 1));
        mx1 = fmaxf(mx1, __shfl_xor_sync(0xffffffffu, mx1, 2));
        const float mnew0 = fmaxf(m_r[0], mx0);
        const float mnew1 = fmaxf(m_r[1], mx1);

        // ---- prefetch K(t+1) + kbias(t+1) (commit always, maybe empty) ----
        if (kt + 1 < nkt) {
            int k0n = k0 + 64;
            #pragma unroll
            for (int i = 0; i < 4; i++) {
                int row = ldrow + i * 16;
                cp16(Kn + row * 72 + ldc * 8, Kb + (size_t)(k0n + row) * DKK + ldc * 8);
            }
            if (tid < 64)
                kbias[((kt + 1) & 1) * 64 + tid] = k_mask[(size_t)b * SS + k0n + tid] ? 0.f : -INFINITY;
        }
        cp_commit();   // group: K(t+1)

        // ---- ex2, row sums, P packed directly into A-operand registers ----
        float ps0 = 0.f, ps1 = 0.f;
        uint32_t pf[4][4];
        #pragma unroll
        for (int u = 0; u < 8; u++) {
            float p0 = ex2f(sacc[u][0] - mnew0);
            float p1 = ex2f(sacc[u][1] - mnew0);
            float p2 = ex2f(sacc[u][2] - mnew1);
            float p3 = ex2f(sacc[u][3] - mnew1);
            ps0 += p0 + p1;
            ps1 += p2 + p3;
            const int s = u >> 1;
            if ((u & 1) == 0) { pf[s][0] = packh2(p0, p1); pf[s][1] = packh2(p2, p3); }
            else              { pf[s][2] = packh2(p0, p1); pf[s][3] = packh2(p2, p3); }
        }
        ps0 += __shfl_xor_sync(0xffffffffu, ps0, 1);
        ps0 += __shfl_xor_sync(0xffffffffu, ps0, 2);
        ps1 += __shfl_xor_sync(0xffffffffu, ps1, 1);
        ps1 += __shfl_xor_sync(0xffffffffu, ps1, 2);

        // ---- l/alpha update + rescale O (before V wait: hides latency) ----
        const float al0 = ex2f(m_r[0] - mnew0);   // NaN iff both -inf (matches ref)
        const float al1 = ex2f(m_r[1] - mnew1);
        l_r[0] = l_r[0] * al0 + ps0; m_r[0] = mnew0;
        l_r[1] = l_r[1] * al1 + ps1; m_r[1] = mnew1;
        #pragma unroll
        for (int u = 0; u < 8; u++) {
            o[u][0] *= al0; o[u][1] *= al0;
            o[u][2] *= al1; o[u][3] *= al1;
        }

        cp_wait1();        // V(t) landed (K(t+1) may still be in flight)
        __syncthreads();   // S4: V visible to all warps

        // ---- O += P @ V (P from registers, V via ldmatrix) ----
        #pragma unroll
        for (int s16 = 0; s16 < 4; s16++) {
            const int ck = s16 * 16;
            uint32_t vb2[8][2];
            #pragma unroll
            for (int up = 0; up < 4; up++) {
                uint32_t tmp[4];
                ldsm_x4(tmp, Vts_b + 2u * ((up * 16 + lh8 + l7) * 72 + ck + l38));
                vb2[2*up][0] = tmp[0]; vb2[2*up][1] = tmp[1];
                vb2[2*up+1][0] = tmp[2]; vb2[2*up+1][1] = tmp[3];
            }
            #pragma unroll
            for (int u = 0; u < 8; u++)
                mma_f16(o[u], pf[s16], vb2[u]);
        }
    }

    // ---- epilogue: normalize, q_mask, write fp16 to g_Ohh ----
    #pragma unroll
    for (int hf = 0; hf < 2; hf++) {
        int row = wid * 16 + grp + 8 * hf;
        int s_ = q0 + row;
        int qm = q_mask[(size_t)b * SS + s_];
        float inv_l = 1.f / l_r[hf];   // NaN rows propagate (matches ref)
        #pragma unroll
        for (int u = 0; u < 8; u++) {
            int dcol = u * 8 + 2 * tig;
            __half2 hv;
            if (qm == 0) {
                hv = __floats2half2_rn(0.f, 0.f);
            } else {
                hv = __floats2half2_rn(o[u][2*hf + 0] * inv_l,
                                       o[u][2*hf + 1] * inv_l);
            }
            *(__half2*)(g_Ohh + ((size_t)b * SS + s_) * DM + h * DKK + dcol) = hv;
        }
    }
}

// ---------------------------------------------------------------------------
extern "C" void kernel_launch(void* const* d_in, const int* in_sizes, int n_in,
                              void* d_out, int out_size)
{
    const float* q  = (const float*)d_in[0];
    const float* k  = (const float*)d_in[1];
    const int*   qm = (const int*)  d_in[2];
    const int*   km = (const int*)  d_in[3];
    const float* Wq = (const float*)d_in[4];
    const float* bq = (const float*)d_in[5];
    const float* Wk = (const float*)d_in[6];
    const float* bk = (const float*)d_in[7];
    const float* Wv = (const float*)d_in[8];
    const float* bv = (const float*)d_in[9];
    const float* Wo = (const float*)d_in[10];
    const float* bo = (const float*)d_in[11];
    const int* causal = (n_in >= 13) ? (const int*)d_in[12] : nullptr;

    __half *Qh, *Kh, *Vt, *Ohh, *qh, *kh, *Wh;
    cudaGetSymbolAddress((void**)&Qh,  g_Qh);
    cudaGetSymbolAddress((void**)&Kh,  g_Kh);
    cudaGetSymbolAddress((void**)&Vt,  g_Vt);
    cudaGetSymbolAddress((void**)&Ohh, g_Ohh);
    cudaGetSymbolAddress((void**)&qh,  g_qh);
    cudaGetSymbolAddress((void**)&kh,  g_kh);
    cudaGetSymbolAddress((void**)&Wh,  g_Wh);

    cudaFuncSetAttribute(gemm_qkv, cudaFuncAttributeMaxDynamicSharedMemorySize,
                         (int)GEMM_SMEM_BYTES);
    cudaFuncSetAttribute(gemm_h, cudaFuncAttributeMaxDynamicSharedMemorySize,
                         (int)GEMM_SMEM_BYTES);
    cudaFuncSetAttribute(flash_attn_h, cudaFuncAttributeMaxDynamicSharedMemorySize,
                         (int)FL_SMEM_BYTES);

    // fused pre-pass: fp32 -> fp16 for all GEMM inputs (one launch, ILP=2)
    cvt_all<<<(NCVT_HALF + 255) / 256, 256>>>(q, k, Wq, Wk, Wv, Wo, qh, kh, Wh);

    // fused Q/K/V projections (projection index fastest-varying for L2 reuse)
    QKVArgs qa;
    qa.xq = qh; qa.xk = kh;
    qa.w0 = Wh + 0 * (size_t)DM * DM; qa.w1 = Wh + 1 * (size_t)DM * DM; qa.w2 = Wh + 2 * (size_t)DM * DM;
    qa.b0 = bq;  qa.b1 = bk;  qa.b2 = bv;
    qa.y0 = Qh;  qa.y1 = Kh;  qa.y2 = Vt;
    dim3 gq(3 * (DM / 128), (BB * SS) / 128);   // (24, 32)
    gemm_qkv<<<gq, 128, GEMM_SMEM_BYTES>>>(qa);

    dim3 ga(SS / 64, NH, BB);                   // (32, 16, 2)
    flash_attn_h<<<ga, 128, FL_SMEM_BYTES>>>(qm, km, causal, 1);

    dim3 gg(DM / 128, (BB * SS) / 128);         // (8, 32)
    gemm_h<<<gg, 128, GEMM_SMEM_BYTES>>>(Ohh, Wh + 3 * (size_t)DM * DM, bo, (float*)d_out);
}